// round 7
// baseline (speedup 1.0000x reference)
#include <cuda_runtime.h>

#define BB   4
#define HH   256
#define WW   256
#define CC   32
#define KF   5
#define NTAP 25

#define TW   16                 // tile width (px)
#define TH   16                 // tile height (2 rows/warp, 8 warps)
#define TSS  258                // u64 stride per tap row (16B aligned, padded)
#define SMEM_BYTES (NTAP * TSS * 8)   // 51600 B

typedef unsigned long long u64;

__device__ __forceinline__ void fma2(u64& d, u64 a, u64 b) {
    asm("fma.rn.f32x2 %0, %1, %2, %0;" : "+l"(d) : "l"(a), "l"(b));
}
__device__ __forceinline__ u64 splat2(float v) {
    unsigned int b = __float_as_uint(v);
    return ((u64)b << 32) | b;
}

// one (feat-window, out-row): 5 taps x 4 px x 4 ch
// acc[8]: px-major, 2 ch-pairs per px. W[16]: 8 cols x 2 ch-pairs.
__device__ __forceinline__ void accum(u64* __restrict__ acc,
                                      const u64* __restrict__ W,
                                      const u64* __restrict__ ts,
                                      int irow, int pix)
{
    #pragma unroll
    for (int j = 0; j < KF; j++) {
        const u64* tp = ts + (irow * KF + j) * TSS + pix;
        const ulonglong2 tA = *(const ulonglong2*)(tp + 0);   // taps px0,px1 (splatted)
        const ulonglong2 tB = *(const ulonglong2*)(tp + 2);   // taps px2,px3
        fma2(acc[0], W[2*(0+j)+0], tA.x);
        fma2(acc[1], W[2*(0+j)+1], tA.x);
        fma2(acc[2], W[2*(1+j)+0], tA.y);
        fma2(acc[3], W[2*(1+j)+1], tA.y);
        fma2(acc[4], W[2*(2+j)+0], tB.x);
        fma2(acc[5], W[2*(2+j)+1], tB.x);
        fma2(acc[6], W[2*(3+j)+0], tB.y);
        fma2(acc[7], W[2*(3+j)+1], tB.y);
    }
}

__global__ void __launch_bounds__(256, 3)
kpc2d_kernel(const float* __restrict__ feat,
             const float* __restrict__ kern,
             const float* __restrict__ bias,
             float* __restrict__ out)
{
    extern __shared__ u64 ts[];   // [NTAP][TSS] splatted taps (t,t)

    const int tid  = threadIdx.x;
    const int lane = tid & 31;
    const int wid  = tid >> 5;          // warp -> rows 2*wid, 2*wid+1
    const int cg   = lane >> 2;         // channel group: ch 4cg..4cg+3
    const int pg   = lane & 3;          // pixel group: px 4pg..4pg+3
    const int w0   = blockIdx.x * TW;
    const int h0   = blockIdx.y * TH;
    const int bz   = blockIdx.z;

    // ---- tap fill (identical to R5): LDG.128 + magic divide + splat STS ----
    const float4* kern4 = (const float4*)kern;
    #pragma unroll 1
    for (unsigned idx4 = tid; idx4 < TH * TW * NTAP / 4; idx4 += 256) {
        const unsigned row = idx4 / 100u;
        const unsigned k4  = (idx4 - row * 100u) * 4u;   // 0..396
        const size_t fidx = ((size_t)((bz * HH + h0 + (int)row) * WW + w0)) * NTAP + k4;
        const float4 v = __ldg(kern4 + (fidx >> 2));
        unsigned col = (k4 * 1311u) >> 15;               // k4/25 for k4<400
        unsigned tap = k4 - col * 25u;
        const unsigned pb = row * TW;
        float vv[4] = {v.x, v.y, v.z, v.w};
        #pragma unroll
        for (int e = 0; e < 4; e++) {
            ts[tap * TSS + pb + col] = splat2(vv[e]);
            if (++tap == 25u) { tap = 0u; col++; }
        }
    }

    const ulonglong2 bv = *(const ulonglong2*)(bias + 4 * cg);
    __syncthreads();

    // ---- compute: thread = 2 rows x 4 px x 4 ch ----
    u64 a0[8], a1[8];
    #pragma unroll
    for (int p = 0; p < 4; p++) {
        a0[2*p] = bv.x; a0[2*p+1] = bv.y;
        a1[2*p] = bv.x; a1[2*p+1] = bv.y;
    }

    const int r0   = wid * 2;
    const int pxb  = pg * 4;
    const int pix0 = r0 * TW + pxb;
    const int pix1 = pix0 + TW;
    const bool interior = (h0 >= 2) && (h0 + TH + 2 <= HH) &&
                          (w0 >= 2) && (w0 + TW + 2 <= WW);

    if (interior) {
        #pragma unroll
        for (int g = 0; g < 6; g++) {
            const int gh = h0 + r0 + g - 2;
            const char* frow = (const char*)
                (feat + ((size_t)((bz * HH + gh) * WW + (w0 + pxb - 2))) * CC + 4 * cg);
            u64 W[16];
            #pragma unroll
            for (int c = 0; c < 8; c++) {
                const ulonglong2 f = __ldg((const ulonglong2*)(frow + c * (CC * 4)));
                W[2*c] = f.x; W[2*c+1] = f.y;
            }
            if (g < 5) accum(a0, W, ts, g,     pix0);
            if (g > 0) accum(a1, W, ts, g - 1, pix1);
        }
    } else {
        #pragma unroll 1
        for (int g = 0; g < 6; g++) {
            const int gh = h0 + r0 + g - 2;
            const bool rok = (unsigned)gh < HH;
            const char* frow = (const char*)
                (feat + ((size_t)((bz * HH + gh) * WW + (w0 + pxb - 2))) * CC + 4 * cg);
            u64 W[16];
            #pragma unroll
            for (int c = 0; c < 8; c++) {
                const int gw = w0 + pxb + c - 2;
                if (rok && (unsigned)gw < WW) {
                    const ulonglong2 f = __ldg((const ulonglong2*)(frow + c * (CC * 4)));
                    W[2*c] = f.x; W[2*c+1] = f.y;
                } else {
                    W[2*c] = 0ULL; W[2*c+1] = 0ULL;
                }
            }
            if (g < 5) accum(a0, W, ts, g,     pix0);
            if (g > 0) accum(a1, W, ts, g - 1, pix1);
        }
    }

    // ---- store: 2 rows x 4 px, STG.128 each (4 ch) ----
    char* o0 = (char*)
        (out + ((size_t)((bz * HH + h0 + r0) * WW + (w0 + pxb))) * CC + 4 * cg);
    char* o1 = o0 + (size_t)WW * CC * 4;
    #pragma unroll
    for (int p = 0; p < 4; p++) {
        ulonglong2 v0; v0.x = a0[2*p]; v0.y = a0[2*p+1];
        ulonglong2 v1; v1.x = a1[2*p]; v1.y = a1[2*p+1];
        *(ulonglong2*)(o0 + p * (CC * 4)) = v0;
        *(ulonglong2*)(o1 + p * (CC * 4)) = v1;
    }
}

extern "C" void kernel_launch(void* const* d_in, const int* in_sizes, int n_in,
                              void* d_out, int out_size)
{
    const float* feat = (const float*)d_in[0];
    const float* kern = (const float*)d_in[1];
    const float* bias = (const float*)d_in[2];
    float* out = (float*)d_out;

    static bool attr_set = false;
    if (!attr_set) {
        cudaFuncSetAttribute(kpc2d_kernel,
                             cudaFuncAttributeMaxDynamicSharedMemorySize,
                             SMEM_BYTES);
        attr_set = true;
    }

    dim3 grid(WW / TW, HH / TH, BB);   // 16 x 16 x 4 = 1024 blocks
    kpc2d_kernel<<<grid, 256, SMEM_BYTES>>>(feat, kern, bias, out);
}

// round 8
// speedup vs baseline: 1.3502x; 1.3502x over previous
#include <cuda_runtime.h>

#define BB   4
#define HH   256
#define WW   256
#define CC   32
#define KF   5
#define NTAP 25

#define TW   16                 // tile width (px)
#define TH   16                 // tile height (2 rows/warp, 8 warps)
#define TSS  258                // u64 stride per tap row (16B aligned, padded)
#define SMEM_BYTES (NTAP * TSS * 8)   // 51600 B

typedef unsigned long long u64;

__device__ __forceinline__ void fma2(u64& d, u64 a, u64 b) {
    asm("fma.rn.f32x2 %0, %1, %2, %0;" : "+l"(d) : "l"(a), "l"(b));
}
__device__ __forceinline__ u64 splat2(float v) {
    unsigned int b = __float_as_uint(v);
    return ((u64)b << 32) | b;
}

// one (feat-window, out-row): 5 j-taps x 8 px x 2 ch
__device__ __forceinline__ void accum(u64* __restrict__ acc,
                                      const u64* __restrict__ W,
                                      const u64* __restrict__ tsrow)
{
    #pragma unroll
    for (int j = 0; j < KF; j++) {
        const u64* tp = tsrow + j * TSS;
        const ulonglong2 t01 = *(const ulonglong2*)(tp + 0);
        const ulonglong2 t23 = *(const ulonglong2*)(tp + 2);
        const ulonglong2 t45 = *(const ulonglong2*)(tp + 4);
        const ulonglong2 t67 = *(const ulonglong2*)(tp + 6);
        fma2(acc[0], W[0 + j], t01.x);
        fma2(acc[1], W[1 + j], t01.y);
        fma2(acc[2], W[2 + j], t23.x);
        fma2(acc[3], W[3 + j], t23.y);
        fma2(acc[4], W[4 + j], t45.x);
        fma2(acc[5], W[5 + j], t45.y);
        fma2(acc[6], W[6 + j], t67.x);
        fma2(acc[7], W[7 + j], t67.y);
    }
}

__global__ void __launch_bounds__(256, 4)
kpc2d_kernel(const float* __restrict__ feat,
             const float* __restrict__ kern,
             const float* __restrict__ bias,
             float* __restrict__ out)
{
    extern __shared__ u64 ts[];   // [NTAP][TSS] splatted taps (t,t)

    const int tid  = threadIdx.x;
    const int lane = tid & 31;
    const int wid  = tid >> 5;          // warp -> rows 2*wid, 2*wid+1
    const int cp   = lane & 15;         // channel pair
    const int half = lane >> 4;         // pixel half
    const int w0   = blockIdx.x * TW;
    const int h0   = blockIdx.y * TH;
    const int bz   = blockIdx.z;

    // ---- tap fill: LDG.128 + magic divide + splat STS (32-bit indexing) ----
    const float4* kern4 = (const float4*)kern;
    const unsigned kbase = (unsigned)((bz * HH + h0) * WW + w0) * NTAP;  // < 2^23
    #pragma unroll 1
    for (unsigned idx4 = tid; idx4 < TH * TW * NTAP / 4; idx4 += 256) {
        const unsigned row = idx4 / 100u;
        const unsigned k4  = (idx4 - row * 100u) * 4u;   // 0..396
        const unsigned fidx = kbase + row * (unsigned)(WW * NTAP) + k4;
        const float4 v = __ldg(kern4 + (fidx >> 2));
        unsigned col = (k4 * 1311u) >> 15;               // k4/25 for k4<400
        unsigned tap = k4 - col * 25u;
        const unsigned pb = row * TW;
        float vv[4] = {v.x, v.y, v.z, v.w};
        #pragma unroll
        for (int e = 0; e < 4; e++) {
            ts[tap * TSS + pb + col] = splat2(vv[e]);
            if (++tap == 25u) { tap = 0u; col++; }
        }
    }

    const ulonglong2 bv2 = *(const ulonglong2*)(bias + 4 * (cp >> 1));
    const u64 bv = (cp & 1) ? bv2.y : bv2.x;
    __syncthreads();

    // ---- compute: thread = 2 rows x 8 px x 2 ch ----
    u64 a0[8], a1[8];
    #pragma unroll
    for (int p = 0; p < 8; p++) { a0[p] = bv; a1[p] = bv; }

    const int r0    = wid * 2;
    const int pbase = half * 8;
    const u64* ts0  = ts + r0 * TW + pbase;          // row-0 tap base
    const u64* ts1  = ts0 + TW;                      // row-1 tap base
    const bool interior = (h0 >= 2) && (h0 + TH + 2 <= HH) &&
                          (w0 >= 2) && (w0 + TW + 2 <= WW);

    // 32-bit element offset of thread's first feat col (row handled per g)
    const int fcol = ((bz * HH) * WW + (w0 + pbase - 2)) * CC + 2 * cp;

    if (interior) {
        #pragma unroll
        for (int g = 0; g < 6; g++) {
            const int gh = h0 + r0 + g - 2;
            const float* frow = feat + (fcol + gh * (WW * CC));
            u64 W[12];
            #pragma unroll
            for (int c = 0; c < 12; c++)
                W[c] = __ldg((const u64*)(frow + c * CC));
            if (g < 5) accum(a0, W, ts0 + g * (KF * TSS));
            if (g > 0) accum(a1, W, ts1 + (g - 1) * (KF * TSS));
        }
    } else {
        #pragma unroll 1
        for (int g = 0; g < 6; g++) {
            const int gh = h0 + r0 + g - 2;
            const bool rok = (unsigned)gh < HH;
            const float* frow = feat + (fcol + gh * (WW * CC));
            u64 W[12];
            #pragma unroll
            for (int c = 0; c < 12; c++) {
                const int gw = w0 + pbase + c - 2;
                W[c] = (rok && (unsigned)gw < WW)
                       ? __ldg((const u64*)(frow + c * CC)) : 0ULL;
            }
            if (g < 5) accum(a0, W, ts0 + g * (KF * TSS));
            if (g > 0) accum(a1, W, ts1 + (g - 1) * (KF * TSS));
        }
    }

    // ---- store: 2 rows x 8 px, STG.64 ----
    float* o0 = out + (((bz * HH + h0 + r0) * WW + (w0 + pbase)) * CC + 2 * cp);
    float* o1 = o0 + WW * CC;
    #pragma unroll
    for (int p = 0; p < 8; p++) {
        *(u64*)(o0 + p * CC) = a0[p];
        *(u64*)(o1 + p * CC) = a1[p];
    }
}

extern "C" void kernel_launch(void* const* d_in, const int* in_sizes, int n_in,
                              void* d_out, int out_size)
{
    const float* feat = (const float*)d_in[0];
    const float* kern = (const float*)d_in[1];
    const float* bias = (const float*)d_in[2];
    float* out = (float*)d_out;

    static bool attr_set = false;
    if (!attr_set) {
        cudaFuncSetAttribute(kpc2d_kernel,
                             cudaFuncAttributeMaxDynamicSharedMemorySize,
                             SMEM_BYTES);
        attr_set = true;
    }

    dim3 grid(WW / TW, HH / TH, BB);   // 16 x 16 x 4 = 1024 blocks
    kpc2d_kernel<<<grid, 256, SMEM_BYTES>>>(feat, kern, bias, out);
}

// round 9
// speedup vs baseline: 1.8815x; 1.3935x over previous
#include <cuda_runtime.h>

#define BB   4
#define HH   256
#define WW   256
#define CC   32
#define KF   5
#define NTAP 25

#define TW   16                 // tile width (px)
#define TH   16                 // tile height (2 rows/warp, 8 warps)
#define TSS  260                // f32 stride per tap row (16B aligned, padded)
#define SMEM_BYTES (NTAP * TSS * 4)   // 26000 B

// one (feat-window, out-row): 5 j-taps x 8 px x 2 ch, scalar FFMA
// acc[16]: px-major (acc[2p+ch]); W[24]: 12 cols x 2 ch; tsp -> taps row base
__device__ __forceinline__ void accum(float* __restrict__ acc,
                                      const float* __restrict__ W,
                                      const float* __restrict__ tsp)
{
    #pragma unroll
    for (int j = 0; j < KF; j++) {
        const float4 tA = *(const float4*)(tsp + j * TSS);       // taps px0..3
        const float4 tB = *(const float4*)(tsp + j * TSS + 4);   // taps px4..7
        acc[ 0] += W[2*(0+j)  ] * tA.x;
        acc[ 1] += W[2*(0+j)+1] * tA.x;
        acc[ 2] += W[2*(1+j)  ] * tA.y;
        acc[ 3] += W[2*(1+j)+1] * tA.y;
        acc[ 4] += W[2*(2+j)  ] * tA.z;
        acc[ 5] += W[2*(2+j)+1] * tA.z;
        acc[ 6] += W[2*(3+j)  ] * tA.w;
        acc[ 7] += W[2*(3+j)+1] * tA.w;
        acc[ 8] += W[2*(4+j)  ] * tB.x;
        acc[ 9] += W[2*(4+j)+1] * tB.x;
        acc[10] += W[2*(5+j)  ] * tB.y;
        acc[11] += W[2*(5+j)+1] * tB.y;
        acc[12] += W[2*(6+j)  ] * tB.z;
        acc[13] += W[2*(6+j)+1] * tB.z;
        acc[14] += W[2*(7+j)  ] * tB.w;
        acc[15] += W[2*(7+j)+1] * tB.w;
    }
}

__global__ void __launch_bounds__(256, 3)
kpc2d_kernel(const float* __restrict__ feat,
             const float* __restrict__ kern,
             const float* __restrict__ bias,
             float* __restrict__ out)
{
    extern __shared__ float ts[];   // [NTAP][TSS] scalar taps

    const int tid  = threadIdx.x;
    const int lane = tid & 31;
    const int wid  = tid >> 5;          // warp -> rows 2*wid, 2*wid+1
    const int cp   = lane & 15;         // channel pair: ch 2cp, 2cp+1
    const int half = lane >> 4;         // pixel half
    const int w0   = blockIdx.x * TW;
    const int h0   = blockIdx.y * TH;
    const int bz   = blockIdx.z;

    // ---- tap fill: LDG.128 + magic divide + scalar transposed STS ----
    const float4* kern4 = (const float4*)kern;
    const unsigned kbase = (unsigned)((bz * HH + h0) * WW + w0) * NTAP;
    #pragma unroll 1
    for (unsigned idx4 = tid; idx4 < TH * TW * NTAP / 4; idx4 += 256) {
        const unsigned row = idx4 / 100u;
        const unsigned k4  = (idx4 - row * 100u) * 4u;   // 0..396
        const unsigned fidx = kbase + row * (unsigned)(WW * NTAP) + k4;
        const float4 v = __ldg(kern4 + (fidx >> 2));
        unsigned col = (k4 * 1311u) >> 15;               // k4/25 for k4<400
        unsigned tap = k4 - col * 25u;
        const unsigned pb = row * TW;
        float vv[4] = {v.x, v.y, v.z, v.w};
        #pragma unroll
        for (int e = 0; e < 4; e++) {
            ts[tap * TSS + pb + col] = vv[e];
            if (++tap == 25u) { tap = 0u; col++; }
        }
    }

    const float2 bv = *(const float2*)(bias + 2 * cp);
    __syncthreads();

    // ---- compute: thread = 2 rows x 8 px x 2 ch, scalar FFMA ----
    float a0[16], a1[16];
    #pragma unroll
    for (int p = 0; p < 8; p++) {
        a0[2*p] = bv.x; a0[2*p+1] = bv.y;
        a1[2*p] = bv.x; a1[2*p+1] = bv.y;
    }

    const int r0    = wid * 2;
    const int pbase = half * 8;
    const float* ts0 = ts + r0 * TW + pbase;   // row-0 tap pixel base
    const float* ts1 = ts0 + TW;               // row-1 tap pixel base
    const bool interior = (h0 >= 2) && (h0 + TH + 2 <= HH) &&
                          (w0 >= 2) && (w0 + TW + 2 <= WW);

    const int fcol = ((bz * HH) * WW + (w0 + pbase - 2)) * CC + 2 * cp;

    if (interior) {
        #pragma unroll
        for (int g = 0; g < 6; g++) {
            const int gh = h0 + r0 + g - 2;
            const float* frow = feat + (fcol + gh * (WW * CC));
            float W[24];
            #pragma unroll
            for (int c = 0; c < 12; c++) {
                const float2 f = __ldg((const float2*)(frow + c * CC));
                W[2*c] = f.x; W[2*c+1] = f.y;
            }
            if (g < 5) accum(a0, W, ts0 + (g    ) * (KF * TSS));
            if (g > 0) accum(a1, W, ts1 + (g - 1) * (KF * TSS));
        }
    } else {
        #pragma unroll 1
        for (int g = 0; g < 6; g++) {
            const int gh = h0 + r0 + g - 2;
            const bool rok = (unsigned)gh < HH;
            const float* frow = feat + (fcol + gh * (WW * CC));
            float W[24];
            #pragma unroll
            for (int c = 0; c < 12; c++) {
                const int gw = w0 + pbase + c - 2;
                if (rok && (unsigned)gw < WW) {
                    const float2 f = __ldg((const float2*)(frow + c * CC));
                    W[2*c] = f.x; W[2*c+1] = f.y;
                } else {
                    W[2*c] = 0.f; W[2*c+1] = 0.f;
                }
            }
            if (g < 5) accum(a0, W, ts0 + (g    ) * (KF * TSS));
            if (g > 0) accum(a1, W, ts1 + (g - 1) * (KF * TSS));
        }
    }

    // ---- store: 2 rows x 8 px, STG.64 ----
    float* o0 = out + (((bz * HH + h0 + r0) * WW + (w0 + pbase)) * CC + 2 * cp);
    float* o1 = o0 + WW * CC;
    #pragma unroll
    for (int p = 0; p < 8; p++) {
        *(float2*)(o0 + p * CC) = make_float2(a0[2*p], a0[2*p+1]);
        *(float2*)(o1 + p * CC) = make_float2(a1[2*p], a1[2*p+1]);
    }
}

extern "C" void kernel_launch(void* const* d_in, const int* in_sizes, int n_in,
                              void* d_out, int out_size)
{
    const float* feat = (const float*)d_in[0];
    const float* kern = (const float*)d_in[1];
    const float* bias = (const float*)d_in[2];
    float* out = (float*)d_out;

    static bool attr_set = false;
    if (!attr_set) {
        cudaFuncSetAttribute(kpc2d_kernel,
                             cudaFuncAttributeMaxDynamicSharedMemorySize,
                             SMEM_BYTES);
        attr_set = true;
    }

    dim3 grid(WW / TW, HH / TH, BB);   // 16 x 16 x 4 = 1024 blocks
    kpc2d_kernel<<<grid, 256, SMEM_BYTES>>>(feat, kern, bias, out);
}